// round 7
// baseline (speedup 1.0000x reference)
#include <cuda_runtime.h>

#define NB   16
#define NH   32
#define HD   64
#define TT   8192
#define NX   2048
#define TC   512               // t-chunk per CTA
#define NCHUNK (TT / TC)       // 16
#define THREADS 128

// deterministic scratch: partial[bh][chunk][d]  (2 MB, L2-resident)
__device__ float g_partial[NB * NH * NCHUNK * HD];

__global__ __launch_bounds__(THREADS, 8)
void attn_chunk_kernel(const float* __restrict__ q,
                       const float* __restrict__ past_k,
                       const float* __restrict__ past_v)
{
    const int chunk = blockIdx.x;      // 0..15
    const int bh    = blockIdx.y;      // 0..511
    const int tid   = threadIdx.x;

    __shared__ float qs[HD];
    __shared__ float w[TC];            // 2 KB
    __shared__ float red[8 * HD];      // 2 KB

    if (tid < HD)
        qs[tid] = q[(size_t)bh * HD + tid];
    __syncthreads();

    // ---- Phase A: w[t] = sum_d q[d] * K[d, t] over this chunk ----
    // past_k: [B,H,HD,T], contiguous in t
    const float* Kp = past_k + (size_t)bh * HD * TT + (size_t)chunk * TC;
    {
        const int t = tid * 4;         // 128 threads * 4 = 512 = TC
        float4 acc = make_float4(0.f, 0.f, 0.f, 0.f);
        #pragma unroll 16
        for (int d = 0; d < HD; d++) {
            const float4 kk = __ldcs(reinterpret_cast<const float4*>(Kp + (size_t)d * TT + t));
            const float qd = qs[d];
            acc.x = fmaf(qd, kk.x, acc.x);
            acc.y = fmaf(qd, kk.y, acc.y);
            acc.z = fmaf(qd, kk.z, acc.z);
            acc.w = fmaf(qd, kk.w, acc.w);
        }
        *reinterpret_cast<float4*>(&w[t]) = acc;
    }
    __syncthreads();

    // ---- Phase B: partial[d] = sum_{t in chunk} w[t] * V[t, d] ----
    // past_v: [B,H,T,HD], contiguous in d (256B rows)
    const float* Vp = past_v + (size_t)bh * TT * HD + (size_t)chunk * TC * HD;
    const int dg = tid & 15;           // float4 index along d (0..15)
    const int tg = tid >> 4;           // t-stride group (0..7)

    float4 acc = make_float4(0.f, 0.f, 0.f, 0.f);
    #pragma unroll 8
    for (int t = tg; t < TC; t += 8) {
        const float  wt = w[t];
        const float4 vv = __ldcs(reinterpret_cast<const float4*>(Vp + (size_t)t * HD + dg * 4));
        acc.x = fmaf(wt, vv.x, acc.x);
        acc.y = fmaf(wt, vv.y, acc.y);
        acc.z = fmaf(wt, vv.z, acc.z);
        acc.w = fmaf(wt, vv.w, acc.w);
    }
    *reinterpret_cast<float4*>(&red[tg * HD + dg * 4]) = acc;
    __syncthreads();

    if (tid < HD) {
        float s = 0.f;
        #pragma unroll
        for (int g = 0; g < 8; g++) s += red[g * HD + tid];
        g_partial[((size_t)bh * NCHUNK + chunk) * HD + tid] = s;
    }
}

// ---- Reduce: out[bh][d] = sum_c partial[bh][c][d] + (q.k) * v[d] ----
// 64 CTAs x 512 threads: 8 bh per CTA, one thread per output element.
__global__ __launch_bounds__(512)
void attn_reduce_kernel(const float* __restrict__ q,
                        const float* __restrict__ k,
                        const float* __restrict__ v,
                        float* __restrict__ out)
{
    const int g  = threadIdx.x >> 6;               // bh-group within CTA (0..7)
    const int d  = threadIdx.x & 63;
    const int bh = blockIdx.x * 8 + g;             // 64 * 8 = 512
    const size_t base = (size_t)bh * HD;           // == b*NX + h*HD

    __shared__ float prod[8][HD];

    // Issue the 16 independent partial loads FIRST (overlap with q.k below)
    float p[NCHUNK];
    #pragma unroll
    for (int c = 0; c < NCHUNK; c++)
        p[c] = __ldcg(&g_partial[(base * NCHUNK) + (size_t)c * HD + d]);

    const float qd = q[base + d];
    const float kd = k[base + d];
    const float vd = v[base + d];
    prod[g][d] = qd * kd;
    __syncthreads();

    float wc = 0.f;
    #pragma unroll
    for (int i = 0; i < HD; i++) wc += prod[g][i]; // same order for all -> deterministic

    float s = 0.f;
    #pragma unroll
    for (int c = 0; c < NCHUNK; c++) s += p[c];

    out[base + d] = fmaf(wc, vd, s);
}

extern "C" void kernel_launch(void* const* d_in, const int* in_sizes, int n_in,
                              void* d_out, int out_size)
{
    const float* q      = (const float*)d_in[0];
    const float* k      = (const float*)d_in[1];
    const float* v      = (const float*)d_in[2];
    const float* past_k = (const float*)d_in[3];
    const float* past_v = (const float*)d_in[4];
    float* out          = (float*)d_out;

    dim3 grid(NCHUNK, NB * NH);
    attn_chunk_kernel<<<grid, THREADS>>>(q, past_k, past_v);
    attn_reduce_kernel<<<NB * NH / 8, 512>>>(q, k, v, out);
}

// round 8
// speedup vs baseline: 1.0275x; 1.0275x over previous
#include <cuda_runtime.h>

#define NB   16
#define NH   32
#define HD   64
#define TT   8192
#define NX   2048
#define TC   1024              // t-chunk per CTA
#define NCHUNK (TT / TC)       // 8
#define NCTA_CHUNK (NB * NH * NCHUNK)   // 4096
#define NBH  (NB * NH)                  // 512
#define THREADS 256

// deterministic scratch: partial[bh][chunk][d]
__device__ float        g_partial[NBH * NCHUNK * HD];
__device__ unsigned int g_count[NBH];      // zero-init; reset by reducer each run

__global__ __launch_bounds__(THREADS, 4)
void attn_onepass_kernel(const float* __restrict__ q,
                         const float* __restrict__ k,
                         const float* __restrict__ v,
                         const float* __restrict__ past_k,
                         const float* __restrict__ past_v,
                         float* __restrict__ out)
{
    const int bid = blockIdx.x;
    const int tid = threadIdx.x;

    if (bid < NCTA_CHUNK) {
        // ================= streaming chunk CTA (identical to R2 core) ======
        const int bh    = bid >> 3;        // bh-major: all 8 chunks adjacent
        const int chunk = bid & 7;

        __shared__ float qs[HD];
        __shared__ float w[TC];            // 4 KB
        __shared__ float red[16 * HD];     // 4 KB

        if (tid < HD)
            qs[tid] = q[(size_t)bh * HD + tid];
        __syncthreads();

        // ---- Phase A: w[t] = sum_d q[d] * K[d, t] over this chunk ----
        const float* Kp = past_k + (size_t)bh * HD * TT + (size_t)chunk * TC;
        {
            const int t = tid * 4;         // 256 * 4 = 1024 = TC
            float4 acc = make_float4(0.f, 0.f, 0.f, 0.f);
            #pragma unroll 16
            for (int d = 0; d < HD; d++) {
                const float4 kk = __ldcs(reinterpret_cast<const float4*>(Kp + (size_t)d * TT + t));
                const float qd = qs[d];
                acc.x = fmaf(qd, kk.x, acc.x);
                acc.y = fmaf(qd, kk.y, acc.y);
                acc.z = fmaf(qd, kk.z, acc.z);
                acc.w = fmaf(qd, kk.w, acc.w);
            }
            *reinterpret_cast<float4*>(&w[t]) = acc;
        }
        __syncthreads();

        // ---- Phase B: partial[d] = sum_{t in chunk} w[t] * V[t, d] ----
        const float* Vp = past_v + (size_t)bh * TT * HD + (size_t)chunk * TC * HD;
        const int dg = tid & 15;
        const int tg = tid >> 4;

        float4 acc = make_float4(0.f, 0.f, 0.f, 0.f);
        #pragma unroll 8
        for (int t = tg; t < TC; t += 16) {
            const float  wt = w[t];
            const float4 vv = __ldcs(reinterpret_cast<const float4*>(Vp + (size_t)t * HD + dg * 4));
            acc.x = fmaf(wt, vv.x, acc.x);
            acc.y = fmaf(wt, vv.y, acc.y);
            acc.z = fmaf(wt, vv.z, acc.z);
            acc.w = fmaf(wt, vv.w, acc.w);
        }
        *reinterpret_cast<float4*>(&red[tg * HD + dg * 4]) = acc;
        __syncthreads();

        if (tid < HD) {
            float s = 0.f;
            #pragma unroll
            for (int g = 0; g < 16; g++) s += red[g * HD + tid];
            g_partial[((size_t)bh * NCHUNK + chunk) * HD + tid] = s;
        }
        __syncthreads();

        if (tid == 0) {
            __threadfence();                       // release partials
            atomicAdd(&g_count[bh], 1u);
        }
    } else {
        // ================= reducer CTA (dispatched after all chunk CTAs) ===
        const int bh = bid - NCTA_CHUNK;           // 0..511
        const size_t base = (size_t)bh * HD;

        __shared__ float prod[HD];

        // prolog, independent of partials
        float qd = 0.f, kd = 0.f, vd = 0.f;
        if (tid < HD) {
            qd = q[base + tid];
            kd = k[base + tid];
            vd = v[base + tid];
            prod[tid] = qd * kd;
        }

        if (tid == 0) {
            volatile unsigned int* cnt = &g_count[bh];
            while (*cnt < NCHUNK) __nanosleep(128);
            __threadfence();                       // acquire partials
        }
        __syncthreads();                           // broadcast visibility

        if (tid < HD) {
            float wc = 0.f;
            #pragma unroll
            for (int i = 0; i < HD; i++) wc += prod[i];   // fixed order -> deterministic

            float s = 0.f;
            #pragma unroll
            for (int c = 0; c < NCHUNK; c++)
                s += __ldcg(&g_partial[base * NCHUNK + (size_t)c * HD + tid]);

            out[base + tid] = fmaf(wc, vd, s);
        }
        if (tid == 0) g_count[bh] = 0;             // reset for next graph replay
    }
}

extern "C" void kernel_launch(void* const* d_in, const int* in_sizes, int n_in,
                              void* d_out, int out_size)
{
    const float* q      = (const float*)d_in[0];
    const float* k      = (const float*)d_in[1];
    const float* v      = (const float*)d_in[2];
    const float* past_k = (const float*)d_in[3];
    const float* past_v = (const float*)d_in[4];
    float* out          = (float*)d_out;

    attn_onepass_kernel<<<NCTA_CHUNK + NBH, THREADS>>>(q, k, v, past_k, past_v, out);
}